// round 12
// baseline (speedup 1.0000x reference)
#include <cuda_runtime.h>
#include <cstdint>
#include <math.h>

#define B_  128
#define T_  256
#define D_  256
#define U_  256
#define NG  768
#define M_  (B_ * T_)

typedef unsigned long long u64;

__device__ float g_xz[M_ * NG];        // x@kernel + bias
__device__ float g_subo[3 * B_ * T_];  // sub_out[s][b][t]

// ---------------- helpers ------------------------------------------------
__device__ __forceinline__ u64 pack2(float lo, float hi) {
    u64 r;
    asm("mov.b64 %0, {%1, %2};" : "=l"(r)
        : "r"(__float_as_uint(lo)), "r"(__float_as_uint(hi)));
    return r;
}
__device__ __forceinline__ u64 fma2(u64 a, u64 b, u64 c) {
    u64 d;
    asm("fma.rn.f32x2 %0, %1, %2, %3;" : "=l"(d) : "l"(a), "l"(b), "l"(c));
    return d;
}
__device__ __forceinline__ float2 unpack2(u64 v) {
    uint32_t lo, hi;
    asm("mov.b64 {%0, %1}, %2;" : "=r"(lo), "=r"(hi) : "l"(v));
    return make_float2(__uint_as_float(lo), __uint_as_float(hi));
}
__device__ __forceinline__ uint32_t smem_u32(const void* p) {
    uint32_t a;
    asm("{ .reg .u64 t; cvta.to.shared.u64 t, %1; cvt.u32.u64 %0, t; }"
        : "=r"(a) : "l"(p));
    return a;
}
__device__ __forceinline__ void mbar_init(uint32_t m, uint32_t cnt) {
    asm volatile("mbarrier.init.shared.b64 [%0], %1;" :: "r"(m), "r"(cnt) : "memory");
}
__device__ __forceinline__ void mbar_arm(uint32_t m, uint32_t bytes) {
    asm volatile("mbarrier.arrive.expect_tx.shared.b64 _, [%0], %1;"
                 :: "r"(m), "r"(bytes) : "memory");
}
__device__ __forceinline__ void mbar_wait(uint32_t m, uint32_t parity) {
    asm volatile(
        "{\n\t"
        ".reg .pred P;\n\t"
        "WL%=:\n\t"
        "mbarrier.try_wait.parity.acquire.cluster.shared::cta.b64 P, [%0], %1, 0x989680;\n\t"
        "@P bra WD%=;\n\t"
        "bra WL%=;\n\t"
        "WD%=:\n\t"
        "}"
        :: "r"(m), "r"(parity) : "memory");
}
__device__ __forceinline__ uint32_t mapa_u32(uint32_t laddr, int rank) {
    uint32_t r;
    asm("mapa.shared::cluster.u32 %0, %1, %2;" : "=r"(r) : "r"(laddr), "r"(rank));
    return r;
}
// bulk smem -> remote smem copy, completes remote mbarrier with tx bytes
__device__ __forceinline__ void bulk_to(uint32_t dst_remote, uint32_t src_local,
                                        uint32_t bytes, uint32_t mbar_remote) {
    asm volatile(
        "cp.async.bulk.shared::cluster.shared::cta.mbarrier::complete_tx::bytes "
        "[%0], [%1], %2, [%3];"
        :: "r"(dst_remote), "r"(src_local), "r"(bytes), "r"(mbar_remote) : "memory");
}
// fast transcendentals (MUFU-based; rel err ~1e-6, far under 1e-3 budget)
__device__ __forceinline__ float fast_sig(float x) {
    return __fdividef(1.f, 1.f + __expf(-x));
}
__device__ __forceinline__ float fast_tanh(float x) {
    return 1.f - __fdividef(2.f, __expf(2.f * x) + 1.f);
}

// ---------------------------------------------------------------- k1: GEMM
__global__ __launch_bounds__(256, 2) void k1_gemm(const float* __restrict__ x,
                                                  const float* __restrict__ w,
                                                  const float* __restrict__ bias) {
    __shared__ __align__(16) float As[2][8][132];
    __shared__ __align__(16) float Bs[2][8][128];
    const int tid = threadIdx.x;
    const int n0 = blockIdx.x * 128, m0 = blockIdx.y * 128;
    const int tm = (tid >> 4) * 8, tn = (tid & 15) * 8;
    const int mA = tid >> 1, kq = (tid & 1) * 4;
    const int rB = tid >> 5, cB = (tid & 31) * 4;

    u64 acc2[4][8];
#pragma unroll
    for (int p = 0; p < 4; p++)
#pragma unroll
        for (int j = 0; j < 8; j++) acc2[p][j] = 0ull;

    float4 av = *reinterpret_cast<const float4*>(&x[(m0 + mA) * 256 + kq]);
    float4 bv = *reinterpret_cast<const float4*>(&w[rB * NG + n0 + cB]);

    for (int k0 = 0; k0 < 256; k0 += 8) {
        const int cur = (k0 >> 3) & 1;
        As[cur][kq + 0][mA] = av.x; As[cur][kq + 1][mA] = av.y;
        As[cur][kq + 2][mA] = av.z; As[cur][kq + 3][mA] = av.w;
        *reinterpret_cast<float4*>(&Bs[cur][rB][cB]) = bv;
        __syncthreads();
        if (k0 + 8 < 256) {
            av = *reinterpret_cast<const float4*>(&x[(m0 + mA) * 256 + k0 + 8 + kq]);
            bv = *reinterpret_cast<const float4*>(&w[(k0 + 8 + rB) * NG + n0 + cB]);
        }
#pragma unroll
        for (int k = 0; k < 8; k++) {
            const ulonglong2* ap = reinterpret_cast<const ulonglong2*>(&As[cur][k][tm]);
            const ulonglong2 aA = ap[0], aB = ap[1];
            const u64 a2[4] = {aA.x, aA.y, aB.x, aB.y};
            float b[8];
            *reinterpret_cast<float4*>(b)     = *reinterpret_cast<float4*>(&Bs[cur][k][tn]);
            *reinterpret_cast<float4*>(b + 4) = *reinterpret_cast<float4*>(&Bs[cur][k][tn + 4]);
            u64 b2[8];
#pragma unroll
            for (int j = 0; j < 8; j++) b2[j] = pack2(b[j], b[j]);
#pragma unroll
            for (int p = 0; p < 4; p++)
#pragma unroll
                for (int j = 0; j < 8; j++) acc2[p][j] = fma2(a2[p], b2[j], acc2[p][j]);
        }
    }
    float bi[8];
    *reinterpret_cast<float4*>(bi)     = *reinterpret_cast<const float4*>(&bias[n0 + tn]);
    *reinterpret_cast<float4*>(bi + 4) = *reinterpret_cast<const float4*>(&bias[n0 + tn + 4]);
#pragma unroll
    for (int p = 0; p < 4; p++) {
        float r0[8], r1[8];
#pragma unroll
        for (int j = 0; j < 8; j++) {
            float2 v = unpack2(acc2[p][j]);
            r0[j] = v.x + bi[j];
            r1[j] = v.y + bi[j];
        }
        float* d0 = &g_xz[(size_t)(m0 + tm + 2 * p) * NG + n0 + tn];
        float* d1 = d0 + NG;
#pragma unroll
        for (int j = 0; j < 8; j++) { d0[j] = r0[j]; d1[j] = r1[j]; }
    }
}

// ---------------------------------------------------------------- k2: sub-TKAN/KAN
__global__ __launch_bounds__(256) void k2_sub(const float* __restrict__ x,
                                              const float* __restrict__ stk,
                                              const float* __restrict__ srk,
                                              const float* __restrict__ kbw,
                                              const float* __restrict__ ksw) {
    __shared__ float sw[256 * 9];
    __shared__ float wpart[8];
    __shared__ float bcast;
    const int s = blockIdx.x >> 7, b = blockIdx.x & 127;
    const int d = threadIdx.x, lane = d & 31, wid = d >> 5;

    const float skx = srk[s * 512 + d];
    const float skh = srk[s * 512 + 256 + d];
    const float bw  = kbw[s * 256 + d];
    const float rh  = stk[s * 2 + 0];
    const float rx  = stk[s * 2 + 1];
#pragma unroll
    for (int c = 0; c < 8; c++) sw[d * 9 + c] = ksw[(s * 256 + d) * 8 + c];
    __syncthreads();

    float sub = 0.f;
    const float* xp = x + (b * T_) * D_ + d;
    float* so = g_subo + (s * B_ + b) * T_;

    float xv = __ldg(&xp[0]);
    for (int t = 0; t < T_; t++) {
        const float xn = (t < T_ - 1) ? __ldg(&xp[(t + 1) * D_]) : 0.f;
        const float v = xv * skx + sub * skh;
        float e = v * fast_sig(v) * bw;
        const float xg = (v + 2.2f) * 2.5f;
        const float fj = floorf(xg);
        const int j = (int)fj;
        if (j >= 0 && j <= 10) {
            const float wl = xg - fj, w2 = wl * wl, w3 = w2 * wl;
            const float omw = 1.f - wl;
            const float n0 = (1.f / 6.f) * omw * omw * omw;
            const float n1 = (1.f / 6.f) * (3.f * w3 - 6.f * w2 + 4.f);
            const float n2 = (1.f / 6.f) * (-3.f * w3 + 3.f * w2 + 3.f * wl + 1.f);
            const float n3 = (1.f / 6.f) * w3;
            const int c0 = j - 3;
            const float* swd = &sw[d * 9];
            if (c0     >= 0 && c0     < 8) e += n0 * swd[c0];
            if (c0 + 1 >= 0 && c0 + 1 < 8) e += n1 * swd[c0 + 1];
            if (c0 + 2 >= 0 && c0 + 2 < 8) e += n2 * swd[c0 + 2];
            if (c0 + 3 >= 0 && c0 + 3 < 8) e += n3 * swd[c0 + 3];
        }
#pragma unroll
        for (int off = 16; off > 0; off >>= 1) e += __shfl_xor_sync(0xffffffffu, e, off);
        if (lane == 0) wpart[wid] = e;
        __syncthreads();
        if (d == 0) {
            float tot = 0.f;
#pragma unroll
            for (int ww = 0; ww < 8; ww++) tot += wpart[ww];
            so[t] = tot;
            bcast = rh * tot + rx * sub;
        }
        __syncthreads();
        sub = bcast;
        xv = xn;
    }
}

// ---------------------------------------------------------------- k3: recurrence
// 128 CTAs x 512 threads, cluster 8 (= 8 batches; rank = 32-u tile).
// h layout: hs[buf][(u>>5)*256 + b*32 + (u&31)] so each rank's produced tile
// is one contiguous 1 KB block. Exchange = 8 bulk DSMEM copies per CTA per
// step (one per rank), each completing the remote mbarrier with 1024 tx
// bytes -> 8 mbar updates/step instead of 1024.
__global__ __launch_bounds__(512, 1) __cluster_dims__(8, 1, 1)
void k3_rnn(const float* __restrict__ rk,   // (256,768)
            const float* __restrict__ aw,   // (3,256)
            const float* __restrict__ ab,   // (256)
            float* __restrict__ out) {      // (B,T,U)
    __shared__ __align__(16) float hs[2][2048];
    __shared__ __align__(16) float stage[256];       // my (8b x 32u) h tile
    __shared__ float red[256 * 51];
    __shared__ __align__(8) unsigned long long mbar_s[2];
    const int tid = threadIdx.x;
    const int wid = tid >> 5, lane = tid & 31;
    const int rank_self = blockIdx.x & 7;
    const int u0 = rank_self * 32;
    const int b0 = (blockIdx.x >> 3) * 8;
    const int k0 = wid * 16;

    const uint32_t mb0 = smem_u32(&mbar_s[0]);
    const uint32_t stage_a = smem_u32(&stage[0]);

    // weights: 16 k per warp, packed in pairs along k (once)
    u64 wi2[8], wf2[8], wc2[8];
#pragma unroll
    for (int kk = 0; kk < 8; kk++) {
        const int r0 = (k0 + 2 * kk) * NG + u0 + lane;
        const int r1 = r0 + NG;
        wi2[kk] = pack2(rk[r0],       rk[r1]);
        wf2[kk] = pack2(rk[r0 + 256], rk[r1 + 256]);
        wc2[kk] = pack2(rk[r0 + 512], rk[r1 + 512]);
    }
    // h smem offset for k-slice of batch b: (k0>>5)*256 + b*32 + (k0&31)
    const int hoff_k = (k0 >> 5) * 256 + (k0 & 31);

    // gate-role constants (warps 0-7): thread owns cell (b = wid, u = u0+lane)
    const int gb = b0 + (wid & 7);
    const int gu = u0 + lane;
    const float aw0 = aw[gu], aw1 = aw[256 + gu], aw2 = aw[512 + gu];
    const float abr = ab[gu];
    const float* so0 = g_subo + (0 * B_ + gb) * T_;
    const float* so1 = g_subo + (1 * B_ + gb) * T_;
    const float* so2 = g_subo + (2 * B_ + gb) * T_;
    const float* xzp = g_xz + (size_t)(gb * T_) * NG + gu;
    float* yp = out + (size_t)(gb * T_) * U_ + gu;

    // hoisted remote addresses: my tile lands at hs[buf][rank_self*256]
    uint32_t rdst[8], rmb[8];
    {
        const uint32_t lh = smem_u32(&hs[0][rank_self * 256]);
#pragma unroll
        for (int r = 0; r < 8; r++) {
            rdst[r] = mapa_u32(lh, r);
            rmb[r]  = mapa_u32(mb0, r);
        }
    }

    if (tid == 0) {
        mbar_init(mb0, 1);
        mbar_init(mb0 + 8, 1);
        mbar_arm(mb0, 8192);
        mbar_arm(mb0 + 8, 8192);
    }
    for (int i = tid; i < 2048; i += 512) hs[0][i] = 0.f;
    __syncthreads();
    asm volatile("barrier.cluster.arrive.aligned;\n\t"
                 "barrier.cluster.wait.aligned;" ::: "memory");

    // prefetch gate inputs for t=0
    float xz0, xz1, xz2, s0, s1, s2;
    if (wid < 8) {
        xz0 = __ldg(&xzp[0]);
        xz1 = __ldg(&xzp[256]);
        xz2 = __ldg(&xzp[512]);
        s0 = __ldg(&so0[0]); s1 = __ldg(&so1[0]); s2 = __ldg(&so2[0]);
    }

    float c = 0.f;
    for (int t = 0; t < T_; t++) {
        const int p = t & 1;
        if (t > 0) {
            const uint32_t m = p ? (mb0 + 8) : mb0;
            mbar_wait(m, ((t - 1) >> 1) & 1);
            if (tid == 0) mbar_arm(m, 8192);   // re-arm for step t+1 sends
        }

        // compute role: all 16 warps
#pragma unroll
        for (int b = 0; b < 8; b++) {
            u64 ai = 0ull, af = 0ull, ac = 0ull;
            const ulonglong2* hp =
                reinterpret_cast<const ulonglong2*>(&hs[p][hoff_k + b * 32]);
            const ulonglong2 h0 = hp[0], h1 = hp[1];
            ai = fma2(h0.x, wi2[0], ai); af = fma2(h0.x, wf2[0], af); ac = fma2(h0.x, wc2[0], ac);
            ai = fma2(h0.y, wi2[1], ai); af = fma2(h0.y, wf2[1], af); ac = fma2(h0.y, wc2[1], ac);
            ai = fma2(h1.x, wi2[2], ai); af = fma2(h1.x, wf2[2], af); ac = fma2(h1.x, wc2[2], ac);
            ai = fma2(h1.y, wi2[3], ai); af = fma2(h1.y, wf2[3], af); ac = fma2(h1.y, wc2[3], ac);
            const ulonglong2 h2 = hp[2], h3 = hp[3];
            ai = fma2(h2.x, wi2[4], ai); af = fma2(h2.x, wf2[4], af); ac = fma2(h2.x, wc2[4], ac);
            ai = fma2(h2.y, wi2[5], ai); af = fma2(h2.y, wf2[5], af); ac = fma2(h2.y, wc2[5], ac);
            ai = fma2(h3.x, wi2[6], ai); af = fma2(h3.x, wf2[6], af); ac = fma2(h3.x, wc2[6], ac);
            ai = fma2(h3.y, wi2[7], ai); af = fma2(h3.y, wf2[7], af); ac = fma2(h3.y, wc2[7], ac);
            const float2 vi = unpack2(ai), vf = unpack2(af), vc = unpack2(ac);
            const int base = (b * 32 + lane) * 51 + wid;
            red[base]      = vi.x + vi.y;
            red[base + 16] = vf.x + vf.y;
            red[base + 32] = vc.x + vc.y;
        }
        __syncthreads();

        // gate role: warps 0-7
        if (wid < 8) {
            float zi = xz0, zf = xz1, zc = xz2;
            const int rbase = (wid * 32 + lane) * 51;
#pragma unroll
            for (int kg = 0; kg < 16; kg++) {
                zi += red[rbase + kg];
                zf += red[rbase + 16 + kg];
                zc += red[rbase + 32 + kg];
            }
            const float ig = fast_sig(zi);
            const float fg = fast_sig(zf);
            c = fg * c + ig * fast_tanh(zc);
            const float o = fast_sig(s0 * aw0 + s1 * aw1 + s2 * aw2 + abr);
            const float h = o * fast_tanh(c);

            if (t < T_ - 1) {
                stage[wid * 32 + lane] = h;                    // [b][u32] tile
                asm volatile("bar.sync 1, 256;" ::: "memory"); // gate warps only
                if (tid == 0) {
                    asm volatile("fence.proxy.async.shared::cta;" ::: "memory");
                    const uint32_t doff = p ? 0u : 8192u;      // target hs[p^1]
                    const uint32_t moff = p ? 0u : 8u;
#pragma unroll
                    for (int r = 0; r < 8; r++)
                        bulk_to(rdst[r] + doff, stage_a, 1024u, rmb[r] + moff);
                }
            }
            yp[(size_t)t * U_] = h;

            if (t < T_ - 1) {   // prefetch next step's gate inputs under the wait
                const size_t o1 = (size_t)(t + 1) * NG;
                xz0 = __ldg(&xzp[o1]);
                xz1 = __ldg(&xzp[o1 + 256]);
                xz2 = __ldg(&xzp[o1 + 512]);
                s0 = __ldg(&so0[t + 1]); s1 = __ldg(&so1[t + 1]); s2 = __ldg(&so2[t + 1]);
            }
        }
    }
    asm volatile("barrier.cluster.arrive.aligned;\n\t"
                 "barrier.cluster.wait.aligned;" ::: "memory");
}

// ---------------------------------------------------------------- launch
extern "C" void kernel_launch(void* const* d_in, const int* in_sizes, int n_in,
                              void* d_out, int out_size) {
    const float* x    = (const float*)d_in[0];
    const float* ker  = (const float*)d_in[1];
    const float* rk   = (const float*)d_in[2];
    const float* bias = (const float*)d_in[3];
    const float* stk  = (const float*)d_in[4];
    const float* srk  = (const float*)d_in[5];
    const float* aw   = (const float*)d_in[6];
    const float* ab   = (const float*)d_in[7];
    const float* kbw  = (const float*)d_in[8];
    const float* ksw  = (const float*)d_in[9];
    float* out = (float*)d_out;

    k1_gemm<<<dim3(NG / 128, M_ / 128), 256>>>(x, ker, bias);
    k2_sub<<<3 * B_, 256>>>(x, stk, srk, kbw, ksw);
    k3_rnn<<<128, 512>>>(rk, aw, ab, out);
}